// round 2
// baseline (speedup 1.0000x reference)
#include <cuda_runtime.h>
#include <cuda_bf16.h>
#include <math.h>

// Problem constants (fixed by the dataset)
#define N_NODES    100000
#define N_EDGES    1600000
#define HIDDEN     64
#define NUM_GRAPHS 512

// Scratch (no allocations allowed -> __device__ globals)
__device__ float        g_p[N_NODES];      // x . W_rel  (later reused as exp(score-m))
__device__ float        g_score[N_NODES];  // x . W_root + b_rel, then += sum_edges p[src]
__device__ unsigned int g_m[NUM_GRAPHS];   // per-graph max (monotone uint key)
__device__ float        g_z[NUM_GRAPHS];   // per-graph sum of exp
__device__ int          g_is64;            // 1 if index buffers are int64, 0 if int32

// ---- index load that tolerates either int32 or int64 buffers ----
__device__ __forceinline__ int load_idx(const void* p, long long i, int is64) {
    if (is64) return (int)((const long long*)p)[i];
    return ((const int*)p)[i];
}

// ---- monotone float<->uint key for atomicMax on floats ----
__device__ __forceinline__ unsigned int fkey(float f) {
    unsigned int u = __float_as_uint(f);
    return (u & 0x80000000u) ? ~u : (u | 0x80000000u);
}
__device__ __forceinline__ float funkey(unsigned int u) {
    unsigned int b = (u & 0x80000000u) ? (u ^ 0x80000000u) : ~u;
    return __uint_as_float(b);
}

// K-1: sniff index dtype from the edge buffer.
// If data is little-endian int64 with values < 2^31, every odd int32 word is 0.
// If data is int32 (uniform in [0, N_NODES)), 64 consecutive odd words being all
// zero has probability ~1e-320. Deterministic for a fixed input.
__global__ void k_sniff(const int* __restrict__ ei32) {
    __shared__ int any_nonzero;
    if (threadIdx.x == 0) any_nonzero = 0;
    __syncthreads();
    // odd positions 1,3,...,127 (well inside the buffer for either dtype)
    int v = ei32[2 * threadIdx.x + 1];
    if (v != 0) atomicOr(&any_nonzero, 1);
    __syncthreads();
    if (threadIdx.x == 0) g_is64 = any_nonzero ? 0 : 1;
}

// K0: init output + scratch scalars
__global__ void k_init(float* __restrict__ out) {
    int i = blockIdx.x * blockDim.x + threadIdx.x;
    if (i < NUM_GRAPHS * HIDDEN) out[i] = 0.0f;
    if (i < NUM_GRAPHS) { g_m[i] = 0u; g_z[i] = 0.0f; }  // all fkeys > 0, so 0 is identity
}

// K1: per-node dots. One warp per node; lane l handles cols l and l+32.
__global__ void k_node_dots(const float* __restrict__ x,
                            const float* __restrict__ W_rel,
                            const float* __restrict__ b_rel,
                            const float* __restrict__ W_root) {
    int w   = (blockIdx.x * blockDim.x + threadIdx.x) >> 5;
    int lid = threadIdx.x & 31;
    if (w >= N_NODES) return;
    float x0 = x[w * HIDDEN + lid];
    float x1 = x[w * HIDDEN + 32 + lid];
    float sr = x0 * __ldg(&W_rel[lid])  + x1 * __ldg(&W_rel[32 + lid]);
    float so = x0 * __ldg(&W_root[lid]) + x1 * __ldg(&W_root[32 + lid]);
    #pragma unroll
    for (int off = 16; off > 0; off >>= 1) {
        sr += __shfl_down_sync(0xFFFFFFFFu, sr, off);
        so += __shfl_down_sync(0xFFFFFFFFu, so, off);
    }
    if (lid == 0) {
        g_p[w]     = sr;
        g_score[w] = so + __ldg(&b_rel[0]);
    }
}

// K2: edge scatter of the scalar p: score[dst] += p[src]
__global__ void k_edges(const void* __restrict__ edge_index) {
    int e = blockIdx.x * blockDim.x + threadIdx.x;
    if (e >= N_EDGES) return;
    int is64 = g_is64;                                     // uniform
    int s = load_idx(edge_index, e, is64);                 // src row
    int d = load_idx(edge_index, (long long)N_EDGES + e, is64);  // dst row
    atomicAdd(&g_score[d], g_p[s]);
}

// K3: per-graph max of score (float atomicMax via monotone key)
__global__ void k_seg_max(const void* __restrict__ batch) {
    int i = blockIdx.x * blockDim.x + threadIdx.x;
    if (i >= N_NODES) return;
    int g = load_idx(batch, i, g_is64);
    atomicMax(&g_m[g], fkey(g_score[i]));
}

// K4: e = exp(score - m[g]); z[g] += e. Reuse g_p to hold e.
__global__ void k_exp_sum(const void* __restrict__ batch) {
    int i = blockIdx.x * blockDim.x + threadIdx.x;
    if (i >= N_NODES) return;
    int g = load_idx(batch, i, g_is64);
    float ex = expf(g_score[i] - funkey(g_m[g]));
    g_p[i] = ex;
    atomicAdd(&g_z[g], ex);
}

// K5: out[g, :] += x[i, :] * (e[i] / z[g]).
// batch is SORTED, so accumulate runs in registers and flush only on graph change.
// blockDim = 256 = 4 groups of 64 threads; group handles SUB consecutive nodes,
// thread owns one column.
#define NPB 256            // nodes per block
#define SUB (NPB / 4)      // nodes per 64-thread group
__global__ void k_pool(const float* __restrict__ x,
                       const void* __restrict__ batch,
                       float* __restrict__ out) {
    int col   = threadIdx.x & 63;
    int seg   = threadIdx.x >> 6;
    int start = blockIdx.x * NPB + seg * SUB;
    int end   = min(start + SUB, N_NODES);
    if (start >= N_NODES) return;
    int is64 = g_is64;

    float acc = 0.0f;
    int   cur = -1;
    for (int i = start; i < end; ++i) {
        int g = load_idx(batch, i, is64);      // broadcast load
        if (g != cur) {
            if (cur >= 0) atomicAdd(&out[cur * HIDDEN + col], acc);
            acc = 0.0f;
            cur = g;
        }
        float att = g_p[i] * __frcp_rn(g_z[g]);  // broadcast p, z; fast recip
        acc += x[i * HIDDEN + col] * att;        // coalesced 256B row read
    }
    if (cur >= 0) atomicAdd(&out[cur * HIDDEN + col], acc);
}

extern "C" void kernel_launch(void* const* d_in, const int* in_sizes, int n_in,
                              void* d_out, int out_size) {
    const float* x      = (const float*)d_in[0];
    const void*  ei     = d_in[1];
    const void*  batch  = d_in[2];
    const float* W_rel  = (const float*)d_in[3];
    const float* b_rel  = (const float*)d_in[4];
    const float* W_root = (const float*)d_in[5];
    float*       out    = (float*)d_out;

    (void)in_sizes; (void)n_in; (void)out_size;

    // K-1: dtype sniff (1 block, 64 threads)
    k_sniff<<<1, 64>>>((const int*)ei);

    // K0: init (covers 512*64 output + scalars)
    k_init<<<(NUM_GRAPHS * HIDDEN + 255) / 256, 256>>>(out);

    // K1: node dots — one warp per node
    k_node_dots<<<(N_NODES * 32 + 255) / 256, 256>>>(x, W_rel, b_rel, W_root);

    // K2: edge scalar scatter
    k_edges<<<(N_EDGES + 255) / 256, 256>>>(ei);

    // K3: segment max
    k_seg_max<<<(N_NODES + 255) / 256, 256>>>(batch);

    // K4: exp + segment sum
    k_exp_sum<<<(N_NODES + 255) / 256, 256>>>(batch);

    // K5: weighted pooling with register run-length accumulation
    k_pool<<<(N_NODES + NPB - 1) / NPB, 256>>>(x, batch, out);
}

// round 3
// speedup vs baseline: 2.3762x; 2.3762x over previous
#include <cuda_runtime.h>
#include <cuda_bf16.h>
#include <math.h>

#define N_NODES    100000
#define N_EDGES    1600000
#define HIDDEN     64
#define NUM_GRAPHS 512

// Scratch (no allocations -> __device__ globals)
__device__ float g_p[N_NODES];          // x . W_rel
__device__ float g_score[N_NODES];      // x . W_root + b_rel + sum_edges p[src]
__device__ int   g_start[NUM_GRAPHS + 1]; // per-graph node range starts
__device__ int   g_is64;                // 1 if index buffers are int64

__device__ __forceinline__ int load_idx(const void* p, long long i, int is64) {
    if (is64) return (int)((const long long*)p)[i];
    return ((const int*)p)[i];
}

// ---------- dtype sniff (indices int32 vs int64) ----------
__global__ void k_sniff(const int* __restrict__ ei32) {
    __shared__ int any_nonzero;
    if (threadIdx.x == 0) any_nonzero = 0;
    __syncthreads();
    int v = ei32[2 * threadIdx.x + 1];   // odd int32 words: 0 iff int64<2^31
    if (v != 0) atomicOr(&any_nonzero, 1);
    __syncthreads();
    if (threadIdx.x == 0) g_is64 = any_nonzero ? 0 : 1;
}

// ---------- K1: node dots. 2 nodes per warp, 16 lanes x float4 ----------
__global__ void k_node_dots(const float* __restrict__ x,
                            const float* __restrict__ W_rel,
                            const float* __restrict__ b_rel,
                            const float* __restrict__ W_root) {
    int tid  = blockIdx.x * blockDim.x + threadIdx.x;
    int warp = tid >> 5;
    int lane = threadIdx.x & 31;
    int node = warp * 2 + (lane >> 4);
    int sub  = lane & 15;
    if (node >= N_NODES) return;

    float4 xv = ((const float4*)x)[node * 16 + sub];
    float4 wr = __ldg(((const float4*)W_rel)  + sub);
    float4 wo = __ldg(((const float4*)W_root) + sub);
    float sr = xv.x * wr.x + xv.y * wr.y + xv.z * wr.z + xv.w * wr.w;
    float so = xv.x * wo.x + xv.y * wo.y + xv.z * wo.z + xv.w * wo.w;
    #pragma unroll
    for (int off = 8; off > 0; off >>= 1) {
        sr += __shfl_down_sync(0xFFFFFFFFu, sr, off, 16);
        so += __shfl_down_sync(0xFFFFFFFFu, so, off, 16);
    }
    if (sub == 0) {
        g_p[node]     = sr;
        g_score[node] = so + __ldg(&b_rel[0]);
    }
}

// ---------- K2: edge scatter, 4 edges/thread (int4 fast path) ----------
#define EPT 4
__global__ void k_edges(const void* __restrict__ edge_index) {
    int t  = blockIdx.x * blockDim.x + threadIdx.x;
    int e0 = t * EPT;
    if (e0 >= N_EDGES) return;
    if (!g_is64) {
        const int4* src4 = (const int4*)edge_index;
        const int4* dst4 = (const int4*)((const int*)edge_index + N_EDGES);
        int4 s = src4[t];
        int4 d = dst4[t];
        float p0 = __ldg(&g_p[s.x]);
        float p1 = __ldg(&g_p[s.y]);
        float p2 = __ldg(&g_p[s.z]);
        float p3 = __ldg(&g_p[s.w]);
        atomicAdd(&g_score[d.x], p0);
        atomicAdd(&g_score[d.y], p1);
        atomicAdd(&g_score[d.z], p2);
        atomicAdd(&g_score[d.w], p3);
    } else {
        #pragma unroll
        for (int k = 0; k < EPT; ++k) {
            int e = e0 + k;
            if (e < N_EDGES) {
                int s = load_idx(edge_index, e, 1);
                int d = load_idx(edge_index, (long long)N_EDGES + e, 1);
                atomicAdd(&g_score[d], g_p[s]);
            }
        }
    }
}

// ---------- K3: graph boundary offsets (batch is sorted) ----------
__global__ void k_bounds(const void* __restrict__ batch) {
    int i = blockIdx.x * blockDim.x + threadIdx.x;
    if (i >= N_NODES) return;
    int is64 = g_is64;
    int b = load_idx(batch, i, is64);
    int prev = (i == 0) ? -1 : load_idx(batch, i - 1, is64);
    for (int g = prev + 1; g <= b; ++g) g_start[g] = i;
    if (i == N_NODES - 1) {
        for (int g = b + 1; g <= NUM_GRAPHS; ++g) g_start[g] = N_NODES;
    }
}

// ---------- K4: fused per-graph softmax + weighted pooling ----------
// One block per graph. Phase A: max. Phase B: sum exp. Phase C: pooled output.
__global__ __launch_bounds__(256, 4)
void k_pool(const float* __restrict__ x, float* __restrict__ out) {
    __shared__ float red[256];
    __shared__ float s_m, s_rz;
    int g   = blockIdx.x;
    int tid = threadIdx.x;
    int s   = g_start[g];
    int e   = g_start[g + 1];

    // Phase A: per-graph max of score
    float mx = -INFINITY;
    for (int i = s + tid; i < e; i += 256) mx = fmaxf(mx, g_score[i]);
    red[tid] = mx;
    __syncthreads();
    #pragma unroll
    for (int off = 128; off > 0; off >>= 1) {
        if (tid < off) red[tid] = fmaxf(red[tid], red[tid + off]);
        __syncthreads();
    }
    if (tid == 0) s_m = red[0];
    __syncthreads();
    float m = s_m;

    // Phase B: sum of exp(score - m)
    float sum = 0.0f;
    for (int i = s + tid; i < e; i += 256) sum += __expf(g_score[i] - m);
    red[tid] = sum;
    __syncthreads();
    #pragma unroll
    for (int off = 128; off > 0; off >>= 1) {
        if (tid < off) red[tid] += red[tid + off];
        __syncthreads();
    }
    if (tid == 0) s_rz = (e > s) ? (1.0f / red[0]) : 0.0f;
    __syncthreads();
    float rz = s_rz;

    // Phase C: out[g, col] = sum_i x[i, col] * exp(score[i]-m) * rz
    // 4 groups of 64 threads; group j takes nodes s+j, s+j+4, ...
    int col = tid & 63;
    int grp = tid >> 6;
    float acc = 0.0f;
    for (int i = s + grp; i < e; i += 4) {
        float w = __expf(g_score[i] - m);       // one exp per node per group-partition
        acc += x[i * HIDDEN + col] * w;
    }
    red[tid] = acc;   // red reused as [4][64]
    __syncthreads();
    if (tid < 64) {
        float tot = (red[tid] + red[64 + tid]) + (red[128 + tid] + red[192 + tid]);
        out[g * HIDDEN + tid] = tot * rz;
    }
}

extern "C" void kernel_launch(void* const* d_in, const int* in_sizes, int n_in,
                              void* d_out, int out_size) {
    const float* x      = (const float*)d_in[0];
    const void*  ei     = d_in[1];
    const void*  batch  = d_in[2];
    const float* W_rel  = (const float*)d_in[3];
    const float* b_rel  = (const float*)d_in[4];
    const float* W_root = (const float*)d_in[5];
    float*       out    = (float*)d_out;
    (void)in_sizes; (void)n_in; (void)out_size;

    k_sniff<<<1, 64>>>((const int*)ei);
    // 2 nodes per warp -> 16 nodes per 256-thread block
    k_node_dots<<<(N_NODES + 15) / 16, 256>>>(x, W_rel, b_rel, W_root);
    k_edges<<<(N_EDGES / EPT + 255) / 256, 256>>>(ei);
    k_bounds<<<(N_NODES + 255) / 256, 256>>>(batch);
    k_pool<<<NUM_GRAPHS, 256>>>(x, out);
}

// round 4
// speedup vs baseline: 2.4154x; 1.0165x over previous
#include <cuda_runtime.h>
#include <cuda_bf16.h>
#include <math.h>

#define N_NODES    100000
#define N_EDGES    1600000
#define HIDDEN     64
#define NUM_GRAPHS 512

// Scratch (no allocations -> __device__ globals)
__device__ float g_p[N_NODES];            // x . W_rel
__device__ float g_score[N_NODES];        // x . W_root + b_rel + sum_edges p[src]
__device__ int   g_start[NUM_GRAPHS + 1]; // per-graph node range starts

// ---- inline dtype sniff: odd int32 words of edge buffer are all 0 iff int64 ----
// int32 node indices are uniform in [0,1e5); P(4 specific odd words all zero) ~ 1e-20.
__device__ __forceinline__ int sniff_is64(const int* __restrict__ ei32) {
    int a = ei32[1], b = ei32[3], c = ei32[5], d = ei32[7];  // L1-resident
    return ((a | b) | (c | d)) == 0;
}

__device__ __forceinline__ int load_idx(const void* p, long long i, int is64) {
    if (is64) return (int)((const long long*)p)[i];
    return ((const int*)p)[i];
}

// ---------- K1: fused node dots + graph bounds ----------
// Blocks [0, DOTS_BLOCKS): dots. 2 nodes/warp, 16 lanes x float4.
// Blocks [DOTS_BLOCKS, ...): bounds. 4 nodes/thread, int4 fast path.
#define DOTS_BLOCKS   ((N_NODES + 15) / 16)                 // 6250
#define BOUNDS_BLOCKS ((N_NODES + 4 * 256 - 1) / (4 * 256)) // 98
__global__ void k1_dots_bounds(const float* __restrict__ x,
                               const float* __restrict__ W_rel,
                               const float* __restrict__ b_rel,
                               const float* __restrict__ W_root,
                               const void*  __restrict__ batch,
                               const int*   __restrict__ ei32) {
    if (blockIdx.x < DOTS_BLOCKS) {
        // ---- node dots ----
        int tid  = blockIdx.x * blockDim.x + threadIdx.x;
        int warp = tid >> 5;
        int lane = threadIdx.x & 31;
        int node = warp * 2 + (lane >> 4);
        int sub  = lane & 15;
        if (node >= N_NODES) return;

        float4 xv = ((const float4*)x)[node * 16 + sub];
        float4 wr = __ldg(((const float4*)W_rel)  + sub);
        float4 wo = __ldg(((const float4*)W_root) + sub);
        float sr = xv.x * wr.x + xv.y * wr.y + xv.z * wr.z + xv.w * wr.w;
        float so = xv.x * wo.x + xv.y * wo.y + xv.z * wo.z + xv.w * wo.w;
        #pragma unroll
        for (int off = 8; off > 0; off >>= 1) {
            sr += __shfl_down_sync(0xFFFFFFFFu, sr, off, 16);
            so += __shfl_down_sync(0xFFFFFFFFu, so, off, 16);
        }
        if (sub == 0) {
            g_p[node]     = sr;
            g_score[node] = so + __ldg(&b_rel[0]);
        }
    } else {
        // ---- graph bounds (batch is sorted) ----
        int is64 = sniff_is64(ei32);
        int t  = (blockIdx.x - DOTS_BLOCKS) * blockDim.x + threadIdx.x;
        int i0 = t * 4;
        if (i0 >= N_NODES) return;
        int b0, b1, b2, b3, prev;
        if (!is64 && i0 + 4 <= N_NODES) {
            int4 v = ((const int4*)batch)[t];
            b0 = v.x; b1 = v.y; b2 = v.z; b3 = v.w;
            prev = (i0 == 0) ? -1 : ((const int*)batch)[i0 - 1];
        } else {
            b0 = (i0     < N_NODES) ? load_idx(batch, i0,     is64) : -2;
            b1 = (i0 + 1 < N_NODES) ? load_idx(batch, i0 + 1, is64) : -2;
            b2 = (i0 + 2 < N_NODES) ? load_idx(batch, i0 + 2, is64) : -2;
            b3 = (i0 + 3 < N_NODES) ? load_idx(batch, i0 + 3, is64) : -2;
            prev = (i0 == 0) ? -1 : load_idx(batch, i0 - 1, is64);
        }
        int bs[4] = {b0, b1, b2, b3};
        #pragma unroll
        for (int j = 0; j < 4; ++j) {
            int i = i0 + j;
            if (i >= N_NODES) break;
            int b = bs[j];
            for (int g = prev + 1; g <= b; ++g) g_start[g] = i;
            if (i == N_NODES - 1)
                for (int g = b + 1; g <= NUM_GRAPHS; ++g) g_start[g] = N_NODES;
            prev = b;
        }
    }
}

// ---------- K2: edge scatter, 8 edges/thread ----------
#define EPT 8
__global__ void k_edges(const void* __restrict__ edge_index) {
    int t  = blockIdx.x * blockDim.x + threadIdx.x;
    long long e0 = (long long)t * EPT;
    if (e0 >= N_EDGES) return;
    int is64 = sniff_is64((const int*)edge_index);
    if (!is64) {
        const int4* src4 = (const int4*)edge_index;
        const int4* dst4 = (const int4*)((const int*)edge_index + N_EDGES);
        int4 sa = src4[2 * t];
        int4 sb = src4[2 * t + 1];
        int4 da = dst4[2 * t];
        int4 db = dst4[2 * t + 1];
        float p0 = __ldg(&g_p[sa.x]);
        float p1 = __ldg(&g_p[sa.y]);
        float p2 = __ldg(&g_p[sa.z]);
        float p3 = __ldg(&g_p[sa.w]);
        float p4 = __ldg(&g_p[sb.x]);
        float p5 = __ldg(&g_p[sb.y]);
        float p6 = __ldg(&g_p[sb.z]);
        float p7 = __ldg(&g_p[sb.w]);
        atomicAdd(&g_score[da.x], p0);
        atomicAdd(&g_score[da.y], p1);
        atomicAdd(&g_score[da.z], p2);
        atomicAdd(&g_score[da.w], p3);
        atomicAdd(&g_score[db.x], p4);
        atomicAdd(&g_score[db.y], p5);
        atomicAdd(&g_score[db.z], p6);
        atomicAdd(&g_score[db.w], p7);
    } else {
        #pragma unroll
        for (int k = 0; k < EPT; ++k) {
            long long e = e0 + k;
            if (e < N_EDGES) {
                int s = load_idx(edge_index, e, 1);
                int d = load_idx(edge_index, (long long)N_EDGES + e, 1);
                atomicAdd(&g_score[d], g_p[s]);
            }
        }
    }
}

// ---------- K3: fused per-graph softmax + weighted pooling ----------
__global__ __launch_bounds__(256, 4)
void k_pool(const float* __restrict__ x, float* __restrict__ out) {
    __shared__ float red[256];
    __shared__ float s_m, s_rz;
    int g   = blockIdx.x;
    int tid = threadIdx.x;
    int s   = g_start[g];
    int e   = g_start[g + 1];

    // Phase A: per-graph max of score
    float mx = -INFINITY;
    for (int i = s + tid; i < e; i += 256) mx = fmaxf(mx, g_score[i]);
    red[tid] = mx;
    __syncthreads();
    #pragma unroll
    for (int off = 128; off > 0; off >>= 1) {
        if (tid < off) red[tid] = fmaxf(red[tid], red[tid + off]);
        __syncthreads();
    }
    if (tid == 0) s_m = red[0];
    __syncthreads();
    float m = s_m;

    // Phase B: sum of exp(score - m)
    float sum = 0.0f;
    for (int i = s + tid; i < e; i += 256) sum += __expf(g_score[i] - m);
    red[tid] = sum;
    __syncthreads();
    #pragma unroll
    for (int off = 128; off > 0; off >>= 1) {
        if (tid < off) red[tid] += red[tid + off];
        __syncthreads();
    }
    if (tid == 0) s_rz = (e > s) ? (1.0f / red[0]) : 0.0f;
    __syncthreads();
    float rz = s_rz;

    // Phase C: out[g, col] = rz * sum_i x[i, col] * exp(score[i]-m)
    // 4 groups of 64 threads, stride 4; unrolled x2 for load MLP.
    int col = tid & 63;
    int grp = tid >> 6;
    float acc = 0.0f;
    int i = s + grp;
    for (; i + 4 < e; i += 8) {
        float w0 = __expf(g_score[i]     - m);
        float w1 = __expf(g_score[i + 4] - m);
        float v0 = x[i * HIDDEN + col];
        float v1 = x[(i + 4) * HIDDEN + col];
        acc += v0 * w0 + v1 * w1;
    }
    if (i < e) acc += x[i * HIDDEN + col] * __expf(g_score[i] - m);
    red[tid] = acc;   // red reused as [4][64]
    __syncthreads();
    if (tid < 64) {
        float tot = (red[tid] + red[64 + tid]) + (red[128 + tid] + red[192 + tid]);
        out[g * HIDDEN + tid] = tot * rz;
    }
}

extern "C" void kernel_launch(void* const* d_in, const int* in_sizes, int n_in,
                              void* d_out, int out_size) {
    const float* x      = (const float*)d_in[0];
    const void*  ei     = d_in[1];
    const void*  batch  = d_in[2];
    const float* W_rel  = (const float*)d_in[3];
    const float* b_rel  = (const float*)d_in[4];
    const float* W_root = (const float*)d_in[5];
    float*       out    = (float*)d_out;
    (void)in_sizes; (void)n_in; (void)out_size;

    k1_dots_bounds<<<DOTS_BLOCKS + BOUNDS_BLOCKS, 256>>>(
        x, W_rel, b_rel, W_root, batch, (const int*)ei);
    k_edges<<<(N_EDGES / EPT + 255) / 256, 256>>>(ei);
    k_pool<<<NUM_GRAPHS, 256>>>(x, out);
}